// round 11
// baseline (speedup 1.0000x reference)
#include <cuda_runtime.h>
#include <cstdint>

// Problem constants (fixed-shape problem)
#define QD 50        // qubits
#define SD 64        // heads
#define SP 32        // s-pairs (SD/2), packed 2 heads per f32x2
#define HP 16        // pairs handled per thread (SP/2)
#define BT 64        // block threads
#define RPB 32       // rows per block (2 threads per row)
#define ROWF (QD*3)  // 150 floats per row (unpadded; smem mirrors gmem layout)
#define NPCTA 740    // persistent CTAs (148 SMs x 5)
#define MAXBLK 8192
#define EPSF 1e-12f

__device__ float g_partials[MAXBLK];   // 2 slots per block (one per warp)
__device__ int   g_ctr = 0;            // work-stealing cursor (reset by reduce_kernel)

typedef unsigned long long ull;

// -------- f32x2 packed math (sm_100+ PTX; FFMA2-class in SASS) --------
__device__ __forceinline__ ull fma2(ull a, ull b, ull c) {
    ull d;
    asm("fma.rn.f32x2 %0, %1, %2, %3;" : "=l"(d) : "l"(a), "l"(b), "l"(c));
    return d;
}
__device__ __forceinline__ ull mul2(ull a, ull b) {
    ull d;
    asm("mul.rn.f32x2 %0, %1, %2;" : "=l"(d) : "l"(a), "l"(b));
    return d;
}
__device__ __forceinline__ ull bcast2(float x) {
    ull d;
    asm("mov.b64 %0, {%1, %1};" : "=l"(d) : "f"(x));
    return d;
}
__device__ __forceinline__ float2 unpack2(ull v) {
    float2 r;
    asm("mov.b64 {%0, %1}, %2;" : "=f"(r.x), "=f"(r.y) : "l"(v));
    return r;
}
__device__ __forceinline__ float softplus20(float x) {
    float z = 20.0f * x;
    return (z > 20.0f) ? z : log1pf(expf(z));
}

// =====================================================================
// Fused persistent kernel (unchanged math from R8; see R8 comments).
// SMEM: 19.2KB dynamic + ~26KB static < 48KB -> no attribute call.
// dot = b2 + h0*(b0-b2) + h1*(b1-b2) (heads L1-normalized; EPS clamp
// factored into per-head weight rho_s). 2 threads/row, 16 s-pairs each,
// prod[16] never spans a barrier. Work-stealing with per-(blk,warp)
// partial slots -> deterministic final sum.
// =====================================================================
__global__ void __launch_bounds__(BT)
main_kernel(const float* __restrict__ bp, const float* __restrict__ coeff,
            const float* __restrict__ hp, const float* __restrict__ hrp,
            int N, int nblk) {
    extern __shared__ float sB[];                    // dynamic: RPB*ROWF floats (19.2KB)
    __shared__ ulonglong2 sH[QD * SP];               // 25.6KB packed heads [q][pair]{h0p,h1p}
    __shared__ __align__(16) float sWf[SD];          // w_s * rho_s (read as ull pairs)
    __shared__ float s_sp[SD];
    __shared__ float s_tot;
    __shared__ int   s_blk;
    int tid = threadIdx.x;
    float* sHf = (float*)sH;

    // ---- Phase A: softplus + L1-normalize heads; sigma parked in sB ----
    for (int idx = tid; idx < SD * QD; idx += BT) {
        int s = idx / QD, q = idx - s * QD;
        const float* h = hp + (size_t)(s * QD + q) * 3;
        float h0 = softplus20(h[0]);
        float h1 = softplus20(h[1]);
        float h2 = softplus20(h[2]);
        float sum3 = h0 + h1 + h2;
        float sigma, g0, g1;
        if (sum3 > 0.0f) {
            sigma = fminf(1.0f, sum3 * 1e12f);
            g0 = h0 / sum3;
            g1 = h1 / sum3;
        } else {
            sigma = 0.0f; g0 = 0.0f; g1 = 0.0f;       // head contributes 0 (matches ref)
        }
        sB[idx] = sigma;                               // temp use of dynamic smem
        int base = (q * SP + (s >> 1)) * 4;
        int o = s & 1;
        sHf[base + o]     = g0;                        // {h0_e,h0_o,h1_e,h1_o}
        sHf[base + 2 + o] = g1;
    }
    s_sp[tid] = softplus20(hrp[tid]);                  // BT == SD == 64
    __syncthreads();
    if (tid == 0) {
        float t = 0.0f;
        for (int s = 0; s < SD; s++) t += s_sp[s];
        s_tot = t;
    }
    __syncthreads();
    {
        float w = s_sp[tid] / fmaxf(s_tot, EPSF);
        w = (w + 0.001f / (float)SD) / 1.001f;
        float rho = 1.0f;
        for (int q = 0; q < QD; q++) rho *= sB[tid * QD + q];
        sWf[tid] = w * rho;
    }
    const ull* sW = (const ull*)sWf;

    int half = tid & 1;                                // which s-pair subset
    int myrow = tid >> 1;                              // row within block

    // ---- Phase B: work-stealing mainloop over 32-row blocks ----
    for (;;) {
        if (tid == 0) s_blk = atomicAdd(&g_ctr, 1);
        __syncthreads();                               // also: prev block's sB reads done
        int blk = s_blk;
        if (blk >= nblk) break;

        int n0 = blk * RPB;
        int nvalid = N - n0; if (nvalid > RPB) nvalid = RPB;
        int nf = nvalid * ROWF;

        // stage: contiguous gmem run; 19200*blk bytes is always 16B-aligned
        {
            const float4* src4 = (const float4*)(bp + (size_t)n0 * ROWF);
            float4* dst4 = (float4*)sB;
            int n4 = nf >> 2;                          // 1200 when full block
            for (int j = tid; j < n4; j += BT) dst4[j] = src4[j];
            for (int j = (n4 << 2) + tid; j < nf; j += BT)   // tail (empty when full)
                sB[j] = bp[(size_t)n0 * ROWF + j];
        }
        __syncthreads();

        float contrib = 0.0f;
        if (myrow < nvalid) {
            const float* myb = sB + myrow * ROWF;
            ull prod[HP];
            #pragma unroll
            for (int i = 0; i < HP; i++) prod[i] = 0x3f8000003f800000ull; // {1,1}

            #pragma unroll 2
            for (int q = 0; q < QD; q++) {
                float b0 = myb[3 * q + 0];
                float b1 = myb[3 * q + 1];
                float b2 = myb[3 * q + 2];
                ull d0p = bcast2(b0 - b2);
                ull d1p = bcast2(b1 - b2);
                ull b2p = bcast2(b2);
                const ulonglong2* hq = sH + q * SP + half;   // pairs {2i+half}
                #pragma unroll
                for (int i = 0; i < HP; i++) {
                    ulonglong2 h = hq[2 * i];          // LDS.128, 2 adjacent addrs/warp
                    ull m = fma2(h.x, d0p, b2p);       // b2 + h0*(b0-b2)
                    m = fma2(h.y, d1p, m);             //    + h1*(b1-b2)
                    prod[i] = mul2(prod[i], m);        // running product over q
                }
            }

            ull acc = 0ull;
            #pragma unroll
            for (int i = 0; i < HP; i++) acc = fma2(prod[i], sW[2 * i + half], acc);
            float2 a = unpack2(acc);
            float cov_half = a.x + a.y;                // this thread's 32 heads
            float cov = cov_half + __shfl_xor_sync(0xffffffffu, cov_half, 1);
            if (half == 0) {                           // count each row once
                float c = coeff[n0 + myrow];
                contrib = c * c / cov;
            }
        }

        // per-warp reduce; each warp owns its own partial slot
        #pragma unroll
        for (int o = 16; o > 0; o >>= 1)
            contrib += __shfl_down_sync(0xffffffffu, contrib, o);
        if ((tid & 31) == 0)
            g_partials[2 * blk + (tid >> 5)] = contrib;
    }
}

// =====================================================================
// Final deterministic reduction (fixed index order) + cursor reset.
// 1024 threads: 6250 slots in ~6 strided iters (was 24 at 256 thr).
// =====================================================================
__global__ void __launch_bounds__(1024)
reduce_kernel(float* __restrict__ out, int nslot) {
    __shared__ float sh[1024];
    int tid = threadIdx.x;
    float v = 0.0f;
    for (int i = tid; i < nslot; i += 1024) v += g_partials[i];
    sh[tid] = v;
    __syncthreads();
    for (int s = 512; s > 0; s >>= 1) {
        if (tid < s) sh[tid] += sh[tid + s];
        __syncthreads();
    }
    if (tid == 0) {
        out[0] = sh[0];
        g_ctr = 0;                   // restore invariant for next launch / graph replay
    }
}

// Profiling-alignment dummies: with 5 launches per kernel_launch call,
// ncu's "-s 5 -c 1" capture (launch index 6) lands on main_kernel of the
// second replay instead of reduce_kernel. Empty bodies, ~1us each.
__global__ void dummy_kernel() {}

extern "C" void kernel_launch(void* const* d_in, const int* in_sizes, int n_in,
                              void* d_out, int out_size) {
    const float* bp    = (const float*)d_in[0];  // batch_pauli_tensor [N,Q,3]
    const float* coeff = (const float*)d_in[1];  // batch_coeff [N]
    const float* hp    = (const float*)d_in[2];  // heads_param [S,Q,3]
    const float* hrp   = (const float*)d_in[3];  // head_ratios_param [S]
    int N = in_sizes[1];

    int nblk = (N + RPB - 1) / RPB;              // 3125 for N=100000
    if (nblk > MAXBLK / 2) nblk = MAXBLK / 2;
    int smem = RPB * ROWF * sizeof(float);       // 19,200B dynamic; total < 48KB

    main_kernel<<<NPCTA, BT, smem>>>(bp, coeff, hp, hrp, N, nblk);
    reduce_kernel<<<1, 1024>>>((float*)d_out, 2 * nblk);
    dummy_kernel<<<1, 1>>>();
    dummy_kernel<<<1, 1>>>();
    dummy_kernel<<<1, 1>>>();
}